// round 1
// baseline (speedup 1.0000x reference)
#include <cuda_runtime.h>
#include <cuda_bf16.h>

// out[b,m] = dot(inputs[b,m,:], W[m,:]) + bias[m]
// B=1024, M=2048, I=128 (fp32). Pure HBM-streaming: ~1.08 GB traffic.
// One warp per output row: 32 lanes x float4 = 128 elements, fully coalesced.

#ifndef B_DIM
#define B_DIM 1024
#endif
#ifndef M_DIM
#define M_DIM 2048
#endif
#ifndef I_DIM
#define I_DIM 128
#endif

static constexpr int WARPS_PER_BLOCK = 8;
static constexpr int THREADS_PER_BLOCK = WARPS_PER_BLOCK * 32;

__global__ __launch_bounds__(THREADS_PER_BLOCK)
void diag_linear_kernel(const float4* __restrict__ inp4,   // [B*M*32] float4
                        const float4* __restrict__ w4,     // [M*32] float4
                        const float* __restrict__ bias,    // [M]
                        float* __restrict__ out)           // [B*M]
{
    const int warp_in_block = threadIdx.x >> 5;
    const int lane = threadIdx.x & 31;

    // global row = one (b,m) pair; rows are contiguous: row = b*M + m
    const long long row = (long long)blockIdx.x * WARPS_PER_BLOCK + warp_in_block;
    const long long total_rows = (long long)B_DIM * M_DIM;
    if (row >= total_rows) return;

    const int m = (int)(row & (M_DIM - 1));   // M_DIM is power of 2

    // Each lane: one float4 of the input row + one float4 of the W row.
    const float4 a = inp4[row * (I_DIM / 4) + lane];
    const float4 w = __ldg(&w4[(long long)m * (I_DIM / 4) + lane]);

    float sum = a.x * w.x;
    sum = fmaf(a.y, w.y, sum);
    sum = fmaf(a.z, w.z, sum);
    sum = fmaf(a.w, w.w, sum);

    // Warp butterfly reduction
    #pragma unroll
    for (int off = 16; off > 0; off >>= 1)
        sum += __shfl_xor_sync(0xFFFFFFFFu, sum, off);

    if (lane == 0)
        out[row] = sum + __ldg(&bias[m]);
}

extern "C" void kernel_launch(void* const* d_in, const int* in_sizes, int n_in,
                              void* d_out, int out_size)
{
    const float4* inp4 = (const float4*)d_in[0];  // inputs [B, M, I] fp32
    const float4* w4   = (const float4*)d_in[1];  // Rk_weight [M, I] fp32
    const float*  bias = (const float*)d_in[2];   // bias [M] fp32
    float* out = (float*)d_out;                   // [B, M] fp32

    const long long total_rows = (long long)B_DIM * M_DIM;      // 2,097,152
    const int grid = (int)((total_rows + WARPS_PER_BLOCK - 1) / WARPS_PER_BLOCK);

    diag_linear_kernel<<<grid, THREADS_PER_BLOCK>>>(inp4, w4, bias, out);
}

// round 4
// speedup vs baseline: 1.3715x; 1.3715x over previous
#include <cuda_runtime.h>
#include <cuda_bf16.h>

// out[b,m] = dot(inputs[b,m,:], W[m,:]) + bias[m]
// B=1024, M=2048, I=128 (fp32). HBM-streaming: ~1.08 GB traffic.
//
// R3: 4 rows per warp, 8 lanes per row. 8 front-batched LDG.128 per warp
// (MLP=8), a single 3-level shfl tree reduces all 4 rows at once
// (vs 5 levels per row in R1). sm_103a has no redux.f32, so shfl it is.

#ifndef B_DIM
#define B_DIM 1024
#endif
#ifndef M_DIM
#define M_DIM 2048
#endif
#ifndef I_DIM
#define I_DIM 128
#endif

static constexpr int WARPS_PER_BLOCK = 8;
static constexpr int THREADS_PER_BLOCK = WARPS_PER_BLOCK * 32;
static constexpr int ROWS_PER_WARP = 4;     // 8 lanes per row
static constexpr int F4_PER_ROW = I_DIM / 4;  // 32 float4 per row
static constexpr int F4_PER_LANE = F4_PER_ROW / 8;  // 4 float4 per lane

__device__ __forceinline__ float dot4(const float4 a, const float4 w) {
    float s = a.x * w.x;
    s = fmaf(a.y, w.y, s);
    s = fmaf(a.z, w.z, s);
    s = fmaf(a.w, w.w, s);
    return s;
}

__global__ __launch_bounds__(THREADS_PER_BLOCK)
void diag_linear_kernel(const float4* __restrict__ inp4,   // [B*M*32] float4
                        const float4* __restrict__ w4,     // [M*32] float4
                        const float* __restrict__ bias,    // [M]
                        float* __restrict__ out)           // [B*M]
{
    const int lane = threadIdx.x & 31;
    const int r = lane >> 3;          // row within warp's 4-row group
    const int c = lane & 7;           // chunk within row

    const long long warp = (long long)blockIdx.x * WARPS_PER_BLOCK + (threadIdx.x >> 5);
    const long long row0 = warp * ROWS_PER_WARP;
    const long long row = row0 + r;

    // row0 is 4-aligned; M_DIM pow2 -> the 4-row group never crosses M boundary.
    const int m = (int)(row & (long long)(M_DIM - 1));

    const float4* __restrict__ ia = inp4 + row * F4_PER_ROW + c;
    const float4* __restrict__ wa = w4 + (long long)m * F4_PER_ROW + c;

    // 8 independent LDG.128 issued up-front (MLP_p1 = 8).
    const float4 a0 = ia[0 * 8];
    const float4 a1 = ia[1 * 8];
    const float4 a2 = ia[2 * 8];
    const float4 a3 = ia[3 * 8];
    const float4 w0 = __ldg(&wa[0 * 8]);
    const float4 w1 = __ldg(&wa[1 * 8]);
    const float4 w2 = __ldg(&wa[2 * 8]);
    const float4 w3 = __ldg(&wa[3 * 8]);

    float s = dot4(a0, w0);
    s += dot4(a1, w1);
    s += dot4(a2, w2);
    s += dot4(a3, w3);

    // 3-level butterfly within each 8-lane group reduces ALL 4 rows at once.
    s += __shfl_xor_sync(0xFFFFFFFFu, s, 4);
    s += __shfl_xor_sync(0xFFFFFFFFu, s, 2);
    s += __shfl_xor_sync(0xFFFFFFFFu, s, 1);

    // Lanes 0,8,16,24 hold rows row0..row0+3 -> 4 consecutive floats, coalesced.
    if (c == 0)
        out[row] = s + __ldg(&bias[m]);
}

extern "C" void kernel_launch(void* const* d_in, const int* in_sizes, int n_in,
                              void* d_out, int out_size)
{
    const float4* inp4 = (const float4*)d_in[0];  // inputs [B, M, I] fp32
    const float4* w4   = (const float4*)d_in[1];  // Rk_weight [M, I] fp32
    const float*  bias = (const float*)d_in[2];   // bias [M] fp32
    float* out = (float*)d_out;                   // [B, M] fp32

    const long long total_rows = (long long)B_DIM * M_DIM;          // 2,097,152
    const long long warps = total_rows / ROWS_PER_WARP;             // 524,288
    const int grid = (int)((warps + WARPS_PER_BLOCK - 1) / WARPS_PER_BLOCK); // 65,536

    diag_linear_kernel<<<grid, THREADS_PER_BLOCK>>>(inp4, w4, bias, out);
}